// round 11
// baseline (speedup 1.0000x reference)
#include <cuda_runtime.h>
#include <cuda_fp16.h>
#include <cstdint>

// Problem constants
#define NN     8192
#define INDIM  256
#define DTOT   128      // OUT_DIM * HEADS
#define NCP    144      // padded GEMM N: 128 outputs + 2 denominators + 14 zero pad
#define MT     128      // M tile
#define KT     64       // K tile
#define NSPLIT 4        // split-K factor
#define KSPLIT 2048     // K per split
#define NKI    32       // K iterations per split

// -------- static device scratch (no allocations allowed) --------
__device__ float     g_h[NN * DTOT];            // 4 MB   h = x @ W^T (fp32)
__device__ float     g_er[2 * NN];              // er per head
__device__ unsigned  g_maxkey[2];               // encoded global max of er per head
__device__ __half    g_g[NCP * NN];             // 2.25 MB  G^T fp16 [NCP][NN]
__device__ float     g_part[(size_t)NSPLIT * NN * NCP];  // 18.9 MB split-K partials

__device__ __forceinline__ uint32_t smem_u32(const void* p) {
    uint32_t a;
    asm("{ .reg .u64 t; cvta.to.shared.u64 t, %1; cvt.u32.u64 %0, t; }" : "=r"(a) : "l"(p));
    return a;
}
#define SWZ(off) ((off) ^ (((off) >> 3) & 0x70))

// ordered-uint encoding for float atomicMax
__device__ __forceinline__ unsigned enc_f(float f) {
    unsigned b = __float_as_uint(f);
    return (b & 0x80000000u) ? ~b : (b | 0x80000000u);
}
__device__ __forceinline__ float dec_f(unsigned k) {
    return (k & 0x80000000u) ? __uint_as_float(k & 0x7FFFFFFFu) : __uint_as_float(~k);
}

// ======================= k1: h = x @ W^T (fp32, register tiled) =======================
__global__ void __launch_bounds__(256) k1_h_gemm(const float* __restrict__ x,
                                                const float* __restrict__ W) {
    if (blockIdx.x == 0 && threadIdx.x < 2) g_maxkey[threadIdx.x] = 0u;  // reset for k2a

    __shared__ __align__(16) float xs[32][132];  // k-major [kk][i]
    __shared__ __align__(16) float ws[32][68];   // k-major [kk][c]
    int tid = threadIdx.x;
    int mtile = blockIdx.x >> 1, ntile = blockIdx.x & 1;
    int i0 = mtile * 128, n0 = ntile * 64;
    int tx = tid & 15, ty = tid >> 4;
    int r0 = ty * 8, c0 = tx * 4;

    float acc[8][4];
#pragma unroll
    for (int m = 0; m < 8; ++m)
#pragma unroll
        for (int n = 0; n < 4; ++n) acc[m][n] = 0.f;

    for (int kc = 0; kc < 8; ++kc) {
        int k0 = kc * 32;
#pragma unroll
        for (int i = 0; i < 4; ++i) {          // x tile: 1024 float4
            int q = tid + i * 256;
            int r = q >> 3, c4 = q & 7;
            float4 v = *(const float4*)(x + (size_t)(i0 + r) * INDIM + k0 + c4 * 4);
            xs[c4 * 4 + 0][r] = v.x; xs[c4 * 4 + 1][r] = v.y;
            xs[c4 * 4 + 2][r] = v.z; xs[c4 * 4 + 3][r] = v.w;
        }
#pragma unroll
        for (int i = 0; i < 2; ++i) {          // W tile: 512 float4
            int q = tid + i * 256;
            int r = q >> 3, c4 = q & 7;
            float4 v = *(const float4*)(W + (size_t)(n0 + r) * INDIM + k0 + c4 * 4);
            ws[c4 * 4 + 0][r] = v.x; ws[c4 * 4 + 1][r] = v.y;
            ws[c4 * 4 + 2][r] = v.z; ws[c4 * 4 + 3][r] = v.w;
        }
        __syncthreads();
#pragma unroll
        for (int kk = 0; kk < 32; ++kk) {
            float4 a0 = *(const float4*)&xs[kk][r0];
            float4 a1 = *(const float4*)&xs[kk][r0 + 4];
            float4 bv = *(const float4*)&ws[kk][c0];
            float a[8] = {a0.x, a0.y, a0.z, a0.w, a1.x, a1.y, a1.z, a1.w};
            float b[4] = {bv.x, bv.y, bv.z, bv.w};
#pragma unroll
            for (int m = 0; m < 8; ++m)
#pragma unroll
                for (int n = 0; n < 4; ++n) acc[m][n] += a[m] * b[n];
        }
        __syncthreads();
    }
#pragma unroll
    for (int m = 0; m < 8; ++m) {
        float4 v = make_float4(acc[m][0], acc[m][1], acc[m][2], acc[m][3]);
        *(float4*)(g_h + (size_t)(i0 + r0 + m) * DTOT + n0 + c0) = v;
    }
}

// ======================= k2a: er[j,h] + global max per head =======================
__global__ void __launch_bounds__(256) k2a_er(const float* __restrict__ attn_r) {
    int tid = threadIdx.x, lane = tid & 31, wid = tid >> 5;
    int j = blockIdx.x * 256 + tid;
    const float* hp = g_h + (size_t)j * DTOT;
    float er0 = 0.f, er1 = 0.f;
#pragma unroll
    for (int d = 0; d < 64; ++d) {
        er0 += hp[d]      * attn_r[d];
        er1 += hp[64 + d] * attn_r[64 + d];
    }
    g_er[j] = er0;
    g_er[NN + j] = er1;

    float m0 = er0, m1 = er1;
#pragma unroll
    for (int o = 16; o; o >>= 1) {
        m0 = fmaxf(m0, __shfl_xor_sync(0xFFFFFFFFu, m0, o));
        m1 = fmaxf(m1, __shfl_xor_sync(0xFFFFFFFFu, m1, o));
    }
    __shared__ float s0[8], s1[8];
    if (lane == 0) { s0[wid] = m0; s1[wid] = m1; }
    __syncthreads();
    if (tid == 0) {
#pragma unroll
        for (int w = 1; w < 8; ++w) { m0 = fmaxf(m0, s0[w]); m1 = fmaxf(m1, s1[w]); }
        m0 = fmaxf(m0, s0[0]); m1 = fmaxf(m1, s1[0]);
        atomicMax(&g_maxkey[0], enc_f(m0));
        atomicMax(&g_maxkey[1], enc_f(m1));
    }
}

// ======================= k2b: G^T = exp(er - max) * h  (fp16) =======================
__global__ void __launch_bounds__(256) k2b_build_g() {
    int j = blockIdx.x * 256 + threadIdx.x;
    float m0 = dec_f(g_maxkey[0]), m1 = dec_f(g_maxkey[1]);
    float E0 = expf(g_er[j] - m0);
    float E1 = expf(g_er[NN + j] - m1);
    const float* hp = g_h + (size_t)j * DTOT;
    float hr[128];
#pragma unroll
    for (int i = 0; i < 32; ++i) {
        float4 v = *(const float4*)(hp + i * 4);
        hr[i * 4 + 0] = v.x; hr[i * 4 + 1] = v.y; hr[i * 4 + 2] = v.z; hr[i * 4 + 3] = v.w;
    }
#pragma unroll
    for (int c = 0; c < 128; ++c) {
        float v = (c < 64 ? E0 : E1) * hr[c];
        g_g[(size_t)c * NN + j] = __float2half(v);
    }
    g_g[(size_t)128 * NN + j] = __float2half(E0);
    g_g[(size_t)129 * NN + j] = __float2half(E1);
#pragma unroll
    for (int c = 130; c < NCP; ++c) g_g[(size_t)c * NN + j] = __float2half(0.f);
}

// ======================= k3: [num|den] = f16(adj) @ G =======================
// A: direct global->register fragments (LDG.64, converted in regs, 1-step prefetch).
// smem: B only, 4 stages x 18432 B (fp16 SW128, 144 rows x 128B).
#define BSTAGE 18432
#define NSTG   4
#define SMEM3  (NSTG * BSTAGE)

__device__ __forceinline__ void stage_loadB(uint32_t Bb, int j0, int tid) {
#pragma unroll
    for (int i = 0; i < 5; ++i) {
        int q = tid + i * 256;
        if (q < NCP * 8) {
            int n = q >> 3, c = q & 7;
            uint32_t dst = Bb + SWZ((uint32_t)(n * 128 + c * 16));
            const void* src = (const char*)g_g + ((size_t)n * NN + j0) * 2 + c * 16;
            asm volatile("cp.async.cg.shared.global [%0], [%1], 16;" :: "r"(dst), "l"(src));
        }
    }
    asm volatile("cp.async.commit_group;" ::: "memory");
}

// A fragment raw loads: rows {r, r+8, r+16, r+24} x col-pairs {c, c+8}
__device__ __forceinline__ void lda_frag(int2 av[8], const int* __restrict__ p) {
    av[0] = *(const int2*)(p);
    av[1] = *(const int2*)(p + 8 * NN);
    av[2] = *(const int2*)(p + 8);
    av[3] = *(const int2*)(p + 8 * NN + 8);
    av[4] = *(const int2*)(p + 16 * NN);
    av[5] = *(const int2*)(p + 24 * NN);
    av[6] = *(const int2*)(p + 16 * NN + 8);
    av[7] = *(const int2*)(p + 24 * NN + 8);
}

__global__ void __launch_bounds__(256, 2) k3_adj_gemm(const int* __restrict__ adj) {
    extern __shared__ char sm3[];
    uint32_t sb = smem_u32(sm3);
    int tid = threadIdx.x, lane = tid & 31, wid = tid >> 5;
    int wm = wid & 3, wn = wid >> 2;          // 4 (M) x 2 (N) warps
    int lt = lane >> 3, lr = lane & 7;
    int mtile = blockIdx.x >> 2, sp = blockIdx.x & 3;
    int i0 = mtile * MT, jb = sp * KSPLIT;

    // A fragment pointer: row = i0 + wm*32 + (lane>>2), col = jb + (lane&3)*2
    const int* ap = adj + (size_t)(i0 + wm * 32 + (lane >> 2)) * NN + jb + (lane & 3) * 2;

    // B ldmatrix per-lane offsets (pre-swizzle)
    uint32_t brow4[4], brow2;
#pragma unroll
    for (int g4 = 0; g4 < 4; ++g4)
        brow4[g4] = (uint32_t)((wn * 72 + g4 * 16 + (lt >> 1) * 8 + lr) * 128 + (lt & 1) * 16);
    brow2 = (uint32_t)((wn * 72 + 64 + lr) * 128 + (lt & 1) * 16);

    float acc[2][9][4];
#pragma unroll
    for (int mf = 0; mf < 2; ++mf)
#pragma unroll
        for (int nf = 0; nf < 9; ++nf)
#pragma unroll
            for (int q = 0; q < 4; ++q) acc[mf][nf][q] = 0.f;

    // prologue: 3 B stages in flight, A fragments for step 0 prefetched
    stage_loadB(sb + 0 * BSTAGE, jb + 0 * KT, tid);
    stage_loadB(sb + 1 * BSTAGE, jb + 1 * KT, tid);
    stage_loadB(sb + 2 * BSTAGE, jb + 2 * KT, tid);
    int2 av[8];
    lda_frag(av, ap);

    for (int it = 0; it < NKI; ++it) {
        if (it < NKI - 2)
            asm volatile("cp.async.wait_group 2;" ::: "memory");
        else if (it == NKI - 2)
            asm volatile("cp.async.wait_group 1;" ::: "memory");
        else
            asm volatile("cp.async.wait_group 0;" ::: "memory");
        __syncthreads();
        if (it + 3 < NKI)
            stage_loadB(sb + ((it + 3) & 3) * BSTAGE, jb + (it + 3) * KT, tid);
        uint32_t Bb = sb + (it & 3) * BSTAGE;

#pragma unroll
        for (int s = 0; s < 4; ++s) {
            // convert prefetched raw adj ints -> fp16x2 A fragments
            uint32_t a[2][4];
#pragma unroll
            for (int mf = 0; mf < 2; ++mf) {
#pragma unroll
                for (int q = 0; q < 4; ++q) {
                    int2 w = av[mf * 4 + q];
                    a[mf][q] = ((uint32_t)w.x | ((uint32_t)w.y << 16)) * 0x3C00u;
                }
            }
            // prefetch next k-step's A (global, stage-independent)
            ap += 16;
            if (it * 4 + s + 1 < NKI * 4) lda_frag(av, ap);

            // B fragments via ldmatrix
            uint32_t kb = (uint32_t)(s * 32);
            uint32_t b[9][2];
#pragma unroll
            for (int g4 = 0; g4 < 4; ++g4) {
                uint32_t bd = Bb + SWZ(brow4[g4] + kb);
                asm volatile("ldmatrix.sync.aligned.m8n8.x4.shared.b16 {%0,%1,%2,%3}, [%4];"
                    : "=r"(b[2 * g4][0]), "=r"(b[2 * g4][1]),
                      "=r"(b[2 * g4 + 1][0]), "=r"(b[2 * g4 + 1][1]) : "r"(bd));
            }
            {
                uint32_t bd = Bb + SWZ(brow2 + kb);
                asm volatile("ldmatrix.sync.aligned.m8n8.x2.shared.b16 {%0,%1}, [%2];"
                    : "=r"(b[8][0]), "=r"(b[8][1]) : "r"(bd));
            }
#pragma unroll
            for (int mf = 0; mf < 2; ++mf)
#pragma unroll
                for (int nf = 0; nf < 9; ++nf)
                    asm volatile(
                        "mma.sync.aligned.m16n8k16.row.col.f32.f16.f16.f32 "
                        "{%0,%1,%2,%3}, {%4,%5,%6,%7}, {%8,%9}, {%0,%1,%2,%3};"
                        : "+f"(acc[mf][nf][0]), "+f"(acc[mf][nf][1]),
                          "+f"(acc[mf][nf][2]), "+f"(acc[mf][nf][3])
                        : "r"(a[mf][0]), "r"(a[mf][1]), "r"(a[mf][2]), "r"(a[mf][3]),
                          "r"(b[nf][0]), "r"(b[nf][1]));
        }
    }

    // epilogue: store split-K partials
    int r0 = i0 + wm * 32 + (lane >> 2);
    int c0 = wn * 72 + (lane & 3) * 2;
    float* base = g_part + (size_t)sp * NN * NCP;
#pragma unroll
    for (int mf = 0; mf < 2; ++mf)
#pragma unroll
        for (int nf = 0; nf < 9; ++nf) {
            int row = r0 + mf * 16, col = c0 + nf * 8;
            *(float2*)(base + (size_t)row * NCP + col) =
                make_float2(acc[mf][nf][0], acc[mf][nf][1]);
            *(float2*)(base + (size_t)(row + 8) * NCP + col) =
                make_float2(acc[mf][nf][2], acc[mf][nf][3]);
        }
}

// ======================= k4: combine splits + divide =======================
__global__ void __launch_bounds__(256) k4_finalize(float* __restrict__ out) {
    int g = blockIdx.x * 256 + threadIdx.x;   // over 8192*128
    int i = g >> 7, c = g & 127;
    int hh = c >> 6;
    float num = 0.f, den = 0.f;
#pragma unroll
    for (int s = 0; s < NSPLIT; ++s) {
        const float* p = g_part + ((size_t)s * NN + i) * NCP;
        num += p[c];
        den += p[128 + hh];
    }
    out[g] = num / den;
}

// ======================= launch =======================
extern "C" void kernel_launch(void* const* d_in, const int* in_sizes, int n_in,
                              void* d_out, int out_size) {
    (void)in_sizes; (void)n_in; (void)out_size;
    const float* x      = (const float*)d_in[0];
    const int*   adj    = (const int*)d_in[1];
    const float* W      = (const float*)d_in[2];
    // d_in[3] = attn_l : cancels in the softmax over j — unused
    const float* attn_r = (const float*)d_in[4];
    float* out = (float*)d_out;

    cudaFuncSetAttribute(k3_adj_gemm, cudaFuncAttributeMaxDynamicSharedMemorySize, SMEM3);

    k1_h_gemm<<<128, 256>>>(x, W);
    k2a_er<<<32, 256>>>(attn_r);
    k2b_build_g<<<32, 256>>>();
    k3_adj_gemm<<<256, 256, SMEM3>>>(adj);
    k4_finalize<<<4096, 256>>>(out);
}

// round 13
// speedup vs baseline: 1.0922x; 1.0922x over previous
#include <cuda_runtime.h>
#include <cuda_fp16.h>
#include <cstdint>

// Problem constants
#define NN     8192
#define INDIM  256
#define DTOT   128      // OUT_DIM * HEADS
#define NCP    144      // padded GEMM N: 128 outputs + 2 denominators + 14 zero pad
#define MT     128      // M tile
#define KT     64       // K tile
#define NSPLIT 4        // split-K factor
#define KSPLIT 2048     // K per split
#define NKI    32       // K iterations per split

// -------- static device scratch (no allocations allowed) --------
__device__ float     g_h[NN * DTOT];            // 4 MB   h = x @ W^T (fp32)
__device__ float     g_er[2 * NN];              // er per head
__device__ unsigned  g_maxkey[2];               // encoded global max of er per head
__device__ __half    g_g[NCP * NN];             // 2.25 MB  G^T fp16 [NCP][NN]
__device__ float     g_part[(size_t)NSPLIT * NN * NCP];  // 18.9 MB split-K partials

__device__ __forceinline__ uint32_t smem_u32(const void* p) {
    uint32_t a;
    asm("{ .reg .u64 t; cvta.to.shared.u64 t, %1; cvt.u32.u64 %0, t; }" : "=r"(a) : "l"(p));
    return a;
}
#define SWZ(off) ((off) ^ (((off) >> 3) & 0x70))

// ordered-uint encoding for float atomicMax
__device__ __forceinline__ unsigned enc_f(float f) {
    unsigned b = __float_as_uint(f);
    return (b & 0x80000000u) ? ~b : (b | 0x80000000u);
}
__device__ __forceinline__ float dec_f(unsigned k) {
    return (k & 0x80000000u) ? __uint_as_float(k & 0x7FFFFFFFu) : __uint_as_float(~k);
}

// ======================= k1: h = x @ W^T (fp32, register tiled) =======================
__global__ void __launch_bounds__(256) k1_h_gemm(const float* __restrict__ x,
                                                const float* __restrict__ W) {
    if (blockIdx.x == 0 && threadIdx.x < 2) g_maxkey[threadIdx.x] = 0u;  // reset for k2a

    __shared__ __align__(16) float xs[32][132];  // k-major [kk][i]
    __shared__ __align__(16) float ws[32][68];   // k-major [kk][c]
    int tid = threadIdx.x;
    int mtile = blockIdx.x >> 1, ntile = blockIdx.x & 1;
    int i0 = mtile * 128, n0 = ntile * 64;
    int tx = tid & 15, ty = tid >> 4;
    int r0 = ty * 8, c0 = tx * 4;

    float acc[8][4];
#pragma unroll
    for (int m = 0; m < 8; ++m)
#pragma unroll
        for (int n = 0; n < 4; ++n) acc[m][n] = 0.f;

    for (int kc = 0; kc < 8; ++kc) {
        int k0 = kc * 32;
#pragma unroll
        for (int i = 0; i < 4; ++i) {          // x tile: 1024 float4
            int q = tid + i * 256;
            int r = q >> 3, c4 = q & 7;
            float4 v = *(const float4*)(x + (size_t)(i0 + r) * INDIM + k0 + c4 * 4);
            xs[c4 * 4 + 0][r] = v.x; xs[c4 * 4 + 1][r] = v.y;
            xs[c4 * 4 + 2][r] = v.z; xs[c4 * 4 + 3][r] = v.w;
        }
#pragma unroll
        for (int i = 0; i < 2; ++i) {          // W tile: 512 float4
            int q = tid + i * 256;
            int r = q >> 3, c4 = q & 7;
            float4 v = *(const float4*)(W + (size_t)(n0 + r) * INDIM + k0 + c4 * 4);
            ws[c4 * 4 + 0][r] = v.x; ws[c4 * 4 + 1][r] = v.y;
            ws[c4 * 4 + 2][r] = v.z; ws[c4 * 4 + 3][r] = v.w;
        }
        __syncthreads();
#pragma unroll
        for (int kk = 0; kk < 32; ++kk) {
            float4 a0 = *(const float4*)&xs[kk][r0];
            float4 a1 = *(const float4*)&xs[kk][r0 + 4];
            float4 bv = *(const float4*)&ws[kk][c0];
            float a[8] = {a0.x, a0.y, a0.z, a0.w, a1.x, a1.y, a1.z, a1.w};
            float b[4] = {bv.x, bv.y, bv.z, bv.w};
#pragma unroll
            for (int m = 0; m < 8; ++m)
#pragma unroll
                for (int n = 0; n < 4; ++n) acc[m][n] += a[m] * b[n];
        }
        __syncthreads();
    }
#pragma unroll
    for (int m = 0; m < 8; ++m) {
        float4 v = make_float4(acc[m][0], acc[m][1], acc[m][2], acc[m][3]);
        *(float4*)(g_h + (size_t)(i0 + r0 + m) * DTOT + n0 + c0) = v;
    }
}

// ======================= k2a: er[j,h] + global max per head =======================
__global__ void __launch_bounds__(256) k2a_er(const float* __restrict__ attn_r) {
    int tid = threadIdx.x, lane = tid & 31, wid = tid >> 5;
    int j = blockIdx.x * 256 + tid;
    const float* hp = g_h + (size_t)j * DTOT;
    float er0 = 0.f, er1 = 0.f;
#pragma unroll
    for (int d = 0; d < 64; ++d) {
        er0 += hp[d]      * attn_r[d];
        er1 += hp[64 + d] * attn_r[64 + d];
    }
    g_er[j] = er0;
    g_er[NN + j] = er1;

    float m0 = er0, m1 = er1;
#pragma unroll
    for (int o = 16; o; o >>= 1) {
        m0 = fmaxf(m0, __shfl_xor_sync(0xFFFFFFFFu, m0, o));
        m1 = fmaxf(m1, __shfl_xor_sync(0xFFFFFFFFu, m1, o));
    }
    __shared__ float s0[8], s1[8];
    if (lane == 0) { s0[wid] = m0; s1[wid] = m1; }
    __syncthreads();
    if (tid == 0) {
#pragma unroll
        for (int w = 1; w < 8; ++w) { m0 = fmaxf(m0, s0[w]); m1 = fmaxf(m1, s1[w]); }
        m0 = fmaxf(m0, s0[0]); m1 = fmaxf(m1, s1[0]);
        atomicMax(&g_maxkey[0], enc_f(m0));
        atomicMax(&g_maxkey[1], enc_f(m1));
    }
}

// ======================= k2b: G^T = exp(er - max) * h  (fp16) =======================
__global__ void __launch_bounds__(256) k2b_build_g() {
    int j = blockIdx.x * 256 + threadIdx.x;
    float m0 = dec_f(g_maxkey[0]), m1 = dec_f(g_maxkey[1]);
    float E0 = expf(g_er[j] - m0);
    float E1 = expf(g_er[NN + j] - m1);
    const float* hp = g_h + (size_t)j * DTOT;
    float hr[128];
#pragma unroll
    for (int i = 0; i < 32; ++i) {
        float4 v = *(const float4*)(hp + i * 4);
        hr[i * 4 + 0] = v.x; hr[i * 4 + 1] = v.y; hr[i * 4 + 2] = v.z; hr[i * 4 + 3] = v.w;
    }
#pragma unroll
    for (int c = 0; c < 128; ++c) {
        float v = (c < 64 ? E0 : E1) * hr[c];
        g_g[(size_t)c * NN + j] = __float2half(v);
    }
    g_g[(size_t)128 * NN + j] = __float2half(E0);
    g_g[(size_t)129 * NN + j] = __float2half(E1);
#pragma unroll
    for (int c = 130; c < NCP; ++c) g_g[(size_t)c * NN + j] = __float2half(0.f);
}

// ======================= k3: [num|den] = f16(adj) @ G =======================
// Stage layout (1024-aligned): B fp16 SW128 (144x128B = 18432) then A int8 (128 rows x 80B pitch = 10240).
// A produced by LDG int4 -> PRMT byte-pack -> STS.32; consumed by ld.shared.u16 -> prmt -> fp16x2 frag.
#define BBYTES  18432
#define APITCH8 80
#define ABYTES8 10240
#define STAGEB  (BBYTES + ABYTES8)   // 28672
#define NSTG    3
#define SMEM3   (NSTG * STAGEB)      // 86016

__device__ __forceinline__ void stage_loadB(uint32_t Bb, int j0, int tid) {
#pragma unroll
    for (int i = 0; i < 5; ++i) {
        int q = tid + i * 256;
        if (q < NCP * 8) {
            int n = q >> 3, c = q & 7;
            uint32_t dst = Bb + SWZ((uint32_t)(n * 128 + c * 16));
            const void* src = (const char*)g_g + ((size_t)n * NN + j0) * 2 + c * 16;
            asm volatile("cp.async.cg.shared.global [%0], [%1], 16;" :: "r"(dst), "l"(src));
        }
    }
    asm volatile("cp.async.commit_group;" ::: "memory");
}

// pack byte0 of 4 ints (values 0/1) into one u32
__device__ __forceinline__ uint32_t pack4(int4 v) {
    uint32_t t0, t1, d;
    asm("prmt.b32 %0, %1, %2, 0x0040;" : "=r"(t0) : "r"((uint32_t)v.x), "r"((uint32_t)v.y));
    asm("prmt.b32 %0, %1, %2, 0x0040;" : "=r"(t1) : "r"((uint32_t)v.z), "r"((uint32_t)v.w));
    asm("prmt.b32 %0, %1, %2, 0x5410;" : "=r"(d)  : "r"(t0), "r"(t1));
    return d;
}

// one k-step: A frags from int8 smem, B frags via ldmatrix, 18 MMAs
__device__ __forceinline__ void do_kstep(uint32_t Bb, uint32_t abase, int ks,
                                         float acc[2][9][4],
                                         const uint32_t brow4[4], uint32_t brow2) {
    uint32_t a[2][4];
#pragma unroll
    for (int mf = 0; mf < 2; ++mf)
#pragma unroll
        for (int q = 0; q < 4; ++q) {
            uint32_t off = abase + (uint32_t)(mf * 16 * APITCH8 + (q & 1) * 8 * APITCH8 +
                                              (q >> 1) * 8 + ks * 16);
            uint32_t v, t;
            asm("ld.shared.u16 %0, [%1];" : "=r"(v) : "r"(off));
            asm("prmt.b32 %0, %1, 0, 0x4140;" : "=r"(t) : "r"(v));
            a[mf][q] = t * 0x3C00u;
        }
    uint32_t kb = (uint32_t)(ks * 32);
    uint32_t b[9][2];
#pragma unroll
    for (int g4 = 0; g4 < 4; ++g4) {
        uint32_t bd = Bb + SWZ(brow4[g4] + kb);
        asm volatile("ldmatrix.sync.aligned.m8n8.x4.shared.b16 {%0,%1,%2,%3}, [%4];"
            : "=r"(b[2 * g4][0]), "=r"(b[2 * g4][1]),
              "=r"(b[2 * g4 + 1][0]), "=r"(b[2 * g4 + 1][1]) : "r"(bd));
    }
    {
        uint32_t bd = Bb + SWZ(brow2 + kb);
        asm volatile("ldmatrix.sync.aligned.m8n8.x2.shared.b16 {%0,%1}, [%2];"
            : "=r"(b[8][0]), "=r"(b[8][1]) : "r"(bd));
    }
#pragma unroll
    for (int mf = 0; mf < 2; ++mf)
#pragma unroll
        for (int nf = 0; nf < 9; ++nf)
            asm volatile(
                "mma.sync.aligned.m16n8k16.row.col.f32.f16.f16.f32 "
                "{%0,%1,%2,%3}, {%4,%5,%6,%7}, {%8,%9}, {%0,%1,%2,%3};"
                : "+f"(acc[mf][nf][0]), "+f"(acc[mf][nf][1]),
                  "+f"(acc[mf][nf][2]), "+f"(acc[mf][nf][3])
                : "r"(a[mf][0]), "r"(a[mf][1]), "r"(a[mf][2]), "r"(a[mf][3]),
                  "r"(b[nf][0]), "r"(b[nf][1]));
}

__global__ void __launch_bounds__(256, 2) k3_adj_gemm(const int* __restrict__ adj) {
    extern __shared__ char sm3[];
    uint32_t sb = smem_u32(sm3);
    int tid = threadIdx.x, lane = tid & 31, wid = tid >> 5;
    int wm = wid & 3, wn = wid >> 2;          // 4 (M) x 2 (N) warps
    int lt = lane >> 3, lr = lane & 7;
    int mtile = blockIdx.x >> 2, sp = blockIdx.x & 3;
    int i0 = mtile * MT, jb = sp * KSPLIT;

    // A producer: thread handles rows (tid>>4) + i*16, int4-chunk (tid&15)
    const int* gbase = adj + (size_t)(i0 + (tid >> 4)) * NN + jb + (tid & 15) * 4;
    uint32_t sAoff = (uint32_t)((tid >> 4) * APITCH8 + (tid & 15) * 4);
    // A consumer per-lane base (within stage A region)
    uint32_t aoff8 = (uint32_t)((wm * 32 + (lane >> 2)) * APITCH8 + (lane & 3) * 2);

    // B ldmatrix per-lane offsets (pre-swizzle)
    uint32_t brow4[4], brow2;
#pragma unroll
    for (int g4 = 0; g4 < 4; ++g4)
        brow4[g4] = (uint32_t)((wn * 72 + g4 * 16 + (lt >> 1) * 8 + lr) * 128 + (lt & 1) * 16);
    brow2 = (uint32_t)((wn * 72 + 64 + lr) * 128 + (lt & 1) * 16);

    float acc[2][9][4];
#pragma unroll
    for (int mf = 0; mf < 2; ++mf)
#pragma unroll
        for (int nf = 0; nf < 9; ++nf)
#pragma unroll
            for (int q = 0; q < 4; ++q) acc[mf][nf][q] = 0.f;

    // prologue: stages 0,1 (B async + A pack)
#pragma unroll
    for (int s = 0; s < 2; ++s) {
        stage_loadB(sb + s * STAGEB, jb + s * KT, tid);
        uint32_t As = sb + s * STAGEB + BBYTES + sAoff;
#pragma unroll
        for (int i = 0; i < 8; ++i) {
            int4 v = *(const int4*)(gbase + (size_t)i * 16 * NN + s * KT);
            uint32_t p = pack4(v);
            asm volatile("st.shared.u32 [%0], %1;" :: "r"(As + i * 16 * APITCH8), "r"(p));
        }
    }

    for (int it = 0; it < NKI; ++it) {
        if (it == NKI - 1)
            asm volatile("cp.async.wait_group 0;" ::: "memory");
        else
            asm volatile("cp.async.wait_group 1;" ::: "memory");
        __syncthreads();

        bool ld = (it + 2 < NKI);
        uint32_t Sw = sb + ((it + 2) % 3) * STAGEB;           // write stage
        const int* gp = gbase + (it + 2) * KT;
        uint32_t Aw = Sw + BBYTES + sAoff;
        if (ld) stage_loadB(Sw, jb + (it + 2) * KT, tid);

        uint32_t Sr = sb + (it % 3) * STAGEB;                 // read stage
        uint32_t abase = Sr + BBYTES + aoff8;

        int4 v0, v1;
        if (ld) { v0 = *(const int4*)(gp); v1 = *(const int4*)(gp + (size_t)16 * NN); }
        do_kstep(Sr, abase, 0, acc, brow4, brow2);
        if (ld) {
            asm volatile("st.shared.u32 [%0], %1;" :: "r"(Aw + 0 * 1280), "r"(pack4(v0)));
            asm volatile("st.shared.u32 [%0], %1;" :: "r"(Aw + 1 * 1280), "r"(pack4(v1)));
            v0 = *(const int4*)(gp + (size_t)32 * NN); v1 = *(const int4*)(gp + (size_t)48 * NN);
        }
        do_kstep(Sr, abase, 1, acc, brow4, brow2);
        if (ld) {
            asm volatile("st.shared.u32 [%0], %1;" :: "r"(Aw + 2 * 1280), "r"(pack4(v0)));
            asm volatile("st.shared.u32 [%0], %1;" :: "r"(Aw + 3 * 1280), "r"(pack4(v1)));
            v0 = *(const int4*)(gp + (size_t)64 * NN); v1 = *(const int4*)(gp + (size_t)80 * NN);
        }
        do_kstep(Sr, abase, 2, acc, brow4, brow2);
        if (ld) {
            asm volatile("st.shared.u32 [%0], %1;" :: "r"(Aw + 4 * 1280), "r"(pack4(v0)));
            asm volatile("st.shared.u32 [%0], %1;" :: "r"(Aw + 5 * 1280), "r"(pack4(v1)));
            v0 = *(const int4*)(gp + (size_t)96 * NN); v1 = *(const int4*)(gp + (size_t)112 * NN);
        }
        do_kstep(Sr, abase, 3, acc, brow4, brow2);
        if (ld) {
            asm volatile("st.shared.u32 [%0], %1;" :: "r"(Aw + 6 * 1280), "r"(pack4(v0)));
            asm volatile("st.shared.u32 [%0], %1;" :: "r"(Aw + 7 * 1280), "r"(pack4(v1)));
        }
    }

    // epilogue: store split-K partials
    int r0 = i0 + wm * 32 + (lane >> 2);
    int c0 = wn * 72 + (lane & 3) * 2;
    float* base = g_part + (size_t)sp * NN * NCP;
#pragma unroll
    for (int mf = 0; mf < 2; ++mf)
#pragma unroll
        for (int nf = 0; nf < 9; ++nf) {
            int row = r0 + mf * 16, col = c0 + nf * 8;
            *(float2*)(base + (size_t)row * NCP + col) =
                make_float2(acc[mf][nf][0], acc[mf][nf][1]);
            *(float2*)(base + (size_t)(row + 8) * NCP + col) =
                make_float2(acc[mf][nf][2], acc[mf][nf][3]);
        }
}

// ======================= k4: combine splits + divide =======================
__global__ void __launch_bounds__(256) k4_finalize(float* __restrict__ out) {
    int g = blockIdx.x * 256 + threadIdx.x;   // over 8192*128
    int i = g >> 7, c = g & 127;
    int hh = c >> 6;
    float num = 0.f, den = 0.f;
#pragma unroll
    for (int s = 0; s < NSPLIT; ++s) {
        const float* p = g_part + ((size_t)s * NN + i) * NCP;
        num += p[c];
        den += p[128 + hh];
    }
    out[g] = num / den;
}

// ======================= launch =======================
extern "C" void kernel_launch(void* const* d_in, const int* in_sizes, int n_in,
                              void* d_out, int out_size) {
    (void)in_sizes; (void)n_in; (void)out_size;
    const float* x      = (const float*)d_in[0];
    const int*   adj    = (const int*)d_in[1];
    const float* W      = (const float*)d_in[2];
    // d_in[3] = attn_l : cancels in the softmax over j — unused
    const float* attn_r = (const float*)d_in[4];
    float* out = (float*)d_out;

    cudaFuncSetAttribute(k3_adj_gemm, cudaFuncAttributeMaxDynamicSharedMemorySize, SMEM3);

    k1_h_gemm<<<128, 256>>>(x, W);
    k2a_er<<<32, 256>>>(attn_r);
    k2b_build_g<<<32, 256>>>();
    k3_adj_gemm<<<256, 256, SMEM3>>>(adj);
    k4_finalize<<<4096, 256>>>(out);
}